// round 9
// baseline (speedup 1.0000x reference)
#include <cuda_runtime.h>
#include <cuda_bf16.h>
#include <math.h>

// Problem constants (match reference)
#define BB 16
#define KK 64
#define HH 160
#define WW 160
#define EPSV 1e-5f

// Scratch: per-(b,k,i) row params and per-(b,k,j) column exp factors.
// P = {cr0, g, g40, pad}: cr0 = den*exp(ay*dy^2 - c*dy*x)  (value of the
// combined row factor at j=0), g = exp(c*dy) (per-step multiplier),
// g40 = exp(40*c*dy) (per-40-step multiplier for thread chunk starts).
__device__ float4 g_P[BB * KK * HH];
__device__ float  g_Ex[BB * KK * WW];

__global__ void precompute_kernel(const float* __restrict__ kp,
                                  const float* __restrict__ psx,
                                  const float* __restrict__ psy,
                                  const float* __restrict__ prho)
{
    int bk = blockIdx.x;       // 0 .. B*K-1
    int t  = threadIdx.x;      // 0 .. 159  (H == W == 160)

    float sx  = psx[0];
    float sy  = psy[0];
    float rho = prho[0];

    float om   = 1.0f - rho * rho;
    float den  = 1.0f / (2.0f * 3.14159265358979323846f * sx * sy * sqrtf(om));
    float num1 = -1.0f / (2.0f * om);
    float ay   = num1 / (sy * sy);
    float ax   = num1 / (sx * sx);
    float c    = rho / (om * sx * sy);

    float x = kp[bk * 2 + 0];
    float y = kp[bk * 2 + 1];

    // Row params for i = t
    float dy  = (float)t - y;
    float cdy = c * dy;
    float4 P;
    P.x = den * expf(ay * dy * dy - cdy * x);  // cr at j = 0
    P.y = expf(cdy);                           // per-step cross multiplier
    P.z = expf(40.0f * cdy);                   // 40-step multiplier
    P.w = 0.0f;
    g_P[bk * HH + t] = P;

    // Column factor for j = t
    float dx = (float)t - x;
    g_Ex[bk * WW + t] = expf(ax * dx * dx);
}

// One CTA per (b, i) row. 256 threads = 64 k-lanes x 4 j-chunks of 40.
// Phase A: compute score values via the multiplicative recurrence into smem.
// Phase B: per-j sum over k -> 1/(sum+eps).
// Phase C: normalize + coalesced float4 stores.
__global__ __launch_bounds__(256)
void recon_map_kernel(float* __restrict__ out)
{
    // 16B-unit XOR swizzle on (k & 7) keeps STS.128 / LDS.128 conflict-free
    // in every phase (quarter-warp lanes always hit 8 distinct bank groups).
    __shared__ float4 sval[KK * 40];   // 40 KB: [k][j4-unit, swizzled]
    __shared__ float4 sinv[40];        // 1/(denom+eps) per j, packed as float4

    int i = blockIdx.x;                // row 0..159
    int b = blockIdx.y;                // batch 0..15
    int t = threadIdx.x;
    int k = t & 63;
    int s = t >> 6;                    // j-chunk 0..3, j0 = 40*s
    int bk = b * KK + k;

    float4 P   = g_P[bk * HH + i];
    float  cr  = P.x;
    float  g   = P.y;
    float  g40 = P.z;
    // Advance recurrence to this thread's chunk start j0 = 40*s.
    if (s & 1) cr *= g40;
    if (s & 2) cr *= g40 * g40;

    const float4* ex4 = reinterpret_cast<const float4*>(g_Ex + bk * WW) + s * 10;
    int sw   = k & 7;
    int base = k * 40;

#pragma unroll
    for (int u = 0; u < 10; ++u) {
        float4 e = ex4[u];
        float4 v;
        v.x = cr * e.x; cr *= g;
        v.y = cr * e.y; cr *= g;
        v.z = cr * e.z; cr *= g;
        v.w = cr * e.w; cr *= g;
        sval[base + (((s * 10) + u) ^ sw)] = v;
    }
    __syncthreads();

    // Phase B: threads 0..39 each own one j4 group (4 columns), sum 64 k's.
    if (t < 40) {
        float4 acc = make_float4(0.f, 0.f, 0.f, 0.f);
#pragma unroll
        for (int kk2 = 0; kk2 < KK; ++kk2) {
            float4 v = sval[kk2 * 40 + (t ^ (kk2 & 7))];
            acc.x += v.x; acc.y += v.y; acc.z += v.z; acc.w += v.w;
        }
        float4 iv;
        iv.x = 1.0f / (acc.x + EPSV);
        iv.y = 1.0f / (acc.y + EPSV);
        iv.z = 1.0f / (acc.z + EPSV);
        iv.w = 1.0f / (acc.w + EPSV);
        sinv[t] = iv;
    }
    __syncthreads();

    // Phase C: normalize and write. Consecutive threads -> consecutive j4
    // units within a k row: coalesced STG.128.
    float4* out4 = reinterpret_cast<float4*>(out);
#pragma unroll
    for (int r = 0; r < 10; ++r) {
        int m  = t + r * 256;          // 0 .. 2559
        int kk2 = m / 40;
        int u  = m - kk2 * 40;
        float4 v  = sval[kk2 * 40 + (u ^ (kk2 & 7))];
        float4 iv = sinv[u];
        v.x *= iv.x; v.y *= iv.y; v.z *= iv.z; v.w *= iv.w;
        out4[((size_t)(b * KK + kk2) * HH + i) * 40 + u] = v;
    }
}

extern "C" void kernel_launch(void* const* d_in, const int* in_sizes, int n_in,
                              void* d_out, int out_size)
{
    const float* kp  = (const float*)d_in[0];  // keypoints [B,K,2]
    const float* sx  = (const float*)d_in[1];  // std_x (scalar)
    const float* sy  = (const float*)d_in[2];  // std_y (scalar)
    const float* rho = (const float*)d_in[3];  // correlation (scalar)
    // d_in[4] = DetectionMap: unused by the reference math (shape only).
    float* out = (float*)d_out;

    precompute_kernel<<<BB * KK, 160>>>(kp, sx, sy, rho);

    dim3 grid(HH, BB);
    recon_map_kernel<<<grid, 256>>>(out);
}

// round 10
// speedup vs baseline: 1.2787x; 1.2787x over previous
#include <cuda_runtime.h>
#include <cuda_bf16.h>
#include <math.h>

// Problem constants (match reference)
#define BB 16
#define KK 64
#define HH 160
#define WW 160
#define EPSV 1e-5f

// Scratch:
//  g_P[b,k,i]  = {cr0, g, -, -}: cr0 = den*exp(ay*dy^2 - c*dy*x) (row factor at
//                j=0), g = exp(c*dy) (per-step cross multiplier in j).
//  g_Ex[b,k,j] = exp(ax*dx^2) (pure column factor).
//  g_Inv[b,i,j]= 1/(sum_k value + eps).
__device__ float4 g_P[BB * KK * HH];
__device__ float  g_Ex[BB * KK * WW];
__device__ float  g_Inv[BB * HH * WW];

__global__ void precompute_kernel(const float* __restrict__ kp,
                                  const float* __restrict__ psx,
                                  const float* __restrict__ psy,
                                  const float* __restrict__ prho)
{
    int bk = blockIdx.x;       // 0 .. B*K-1
    int t  = threadIdx.x;      // 0 .. 159  (H == W == 160)

    float sx  = psx[0];
    float sy  = psy[0];
    float rho = prho[0];

    float om   = 1.0f - rho * rho;
    float den  = 1.0f / (2.0f * 3.14159265358979323846f * sx * sy * sqrtf(om));
    float num1 = -1.0f / (2.0f * om);
    float ay   = num1 / (sy * sy);
    float ax   = num1 / (sx * sx);
    float c    = rho / (om * sx * sy);

    float x = kp[bk * 2 + 0];
    float y = kp[bk * 2 + 1];

    float dy  = (float)t - y;
    float cdy = c * dy;
    float4 P;
    P.x = den * expf(ay * dy * dy - cdy * x);  // cr at j = 0
    P.y = expf(cdy);                           // per-step multiplier g
    P.z = 0.0f;
    P.w = 0.0f;
    g_P[bk * HH + t] = P;

    float dx = (float)t - x;
    g_Ex[bk * WW + t] = expf(ax * dx * dx);
}

// Binary powering: h^l for lane l in [0,32). 4 squarings already done by caller.
__device__ __forceinline__ float pow_lane(float h, float h2, float h4,
                                          float h8, float h16, int l)
{
    float p = 1.0f;
    if (l & 1)  p *= h;
    if (l & 2)  p *= h2;
    if (l & 4)  p *= h4;
    if (l & 8)  p *= h8;
    if (l & 16) p *= h16;
    return p;
}

// Denominator kernel: CTA = (b, i). 8 warps; warp w sums k = 8w..8w+7 into a
// per-warp partial (registers), combined via 5 KB smem. Writes 1/(sum+eps).
__global__ __launch_bounds__(256)
void denom_kernel()
{
    __shared__ float S[8][WW];         // per-warp partial sums, 640B rows

    int i = blockIdx.x;                // row 0..159
    int b = blockIdx.y;                // batch 0..15
    int w = threadIdx.x >> 5;
    int l = threadIdx.x & 31;

    float4 acc  = make_float4(0.f, 0.f, 0.f, 0.f);  // j = 4l .. 4l+3
    float4 acc2 = make_float4(0.f, 0.f, 0.f, 0.f);  // lanes<8: j = 128+4l ..

#pragma unroll
    for (int kk = 0; kk < 8; ++kk) {
        int bk = b * KK + w * 8 + kk;
        float4 P  = g_P[bk * HH + i];
        float cr0 = P.x, g = P.y;
        float g2 = g * g, g3 = g2 * g;
        float h  = g2 * g2;
        float h2 = h * h, h4 = h2 * h2, h8 = h4 * h4, h16 = h8 * h8;
        float p  = pow_lane(h, h2, h4, h8, h16, l);

        const float4* ex4 = reinterpret_cast<const float4*>(g_Ex + bk * WW);
        float4 e   = ex4[l];
        float  crl = cr0 * p;
        acc.x += crl * e.x;
        acc.y += crl * g  * e.y;
        acc.z += crl * g2 * e.z;
        acc.w += crl * g3 * e.w;

        if (l < 8) {
            float4 e2  = ex4[32 + l];
            float  crt = cr0 * (h16 * h16) * p;   // h^(32+l)
            acc2.x += crt * e2.x;
            acc2.y += crt * g  * e2.y;
            acc2.z += crt * g2 * e2.z;
            acc2.w += crt * g3 * e2.w;
        }
    }

    reinterpret_cast<float4*>(S[w])[l] = acc;
    if (l < 8)
        reinterpret_cast<float4*>(S[w])[32 + l] = acc2;
    __syncthreads();

    int t = threadIdx.x;
    if (t < WW) {
        float s = 0.0f;
#pragma unroll
        for (int ww = 0; ww < 8; ++ww) s += S[ww][t];
        g_Inv[(b * HH + i) * WW + t] = 1.0f / (s + EPSV);
    }
}

// Main kernel: no shared memory. CTA = (bk, half-of-i); each warp owns 10 full
// (b,k,i) output rows. Lane l covers j = 4l..4l+3 (+ lanes 0..7: j = 128+4l..).
// Ex is loaded once per warp and reused across the 10 rows.
__global__ __launch_bounds__(256)
void recon_out_kernel(float* __restrict__ out)
{
    int bk = blockIdx.x;               // 0..1023 (b*64 + k)
    int b  = bk >> 6;
    int w  = threadIdx.x >> 5;
    int l  = threadIdx.x & 31;

    const float4* ex4 = reinterpret_cast<const float4*>(g_Ex + bk * WW);
    float4 e  = ex4[l];
    float4 e2 = make_float4(0.f, 0.f, 0.f, 0.f);
    if (l < 8) e2 = ex4[32 + l];

    int i0 = blockIdx.y * 80 + w * 10;

#pragma unroll
    for (int r = 0; r < 10; ++r) {
        int i = i0 + r;
        float4 P  = g_P[bk * HH + i];
        float cr0 = P.x, g = P.y;
        float g2 = g * g, g3 = g2 * g;
        float h  = g2 * g2;
        float h2 = h * h, h4 = h2 * h2, h8 = h4 * h4, h16 = h8 * h8;
        float p  = pow_lane(h, h2, h4, h8, h16, l);

        const float4* inv4 =
            reinterpret_cast<const float4*>(g_Inv + (b * HH + i) * WW);
        float4 iv  = inv4[l];
        float  crl = cr0 * p;

        float4 v;
        v.x = crl * e.x * iv.x;
        v.y = crl * g  * e.y * iv.y;
        v.z = crl * g2 * e.z * iv.z;
        v.w = crl * g3 * e.w * iv.w;

        float4* orow =
            reinterpret_cast<float4*>(out + ((size_t)bk * HH + i) * WW);
        orow[l] = v;

        if (l < 8) {
            float4 iv2 = inv4[32 + l];
            float  crt = cr0 * (h16 * h16) * p;   // h^(32+l)
            float4 v2;
            v2.x = crt * e2.x * iv2.x;
            v2.y = crt * g  * e2.y * iv2.y;
            v2.z = crt * g2 * e2.z * iv2.z;
            v2.w = crt * g3 * e2.w * iv2.w;
            orow[32 + l] = v2;
        }
    }
}

extern "C" void kernel_launch(void* const* d_in, const int* in_sizes, int n_in,
                              void* d_out, int out_size)
{
    const float* kp  = (const float*)d_in[0];  // keypoints [B,K,2]
    const float* sx  = (const float*)d_in[1];  // std_x (scalar)
    const float* sy  = (const float*)d_in[2];  // std_y (scalar)
    const float* rho = (const float*)d_in[3];  // correlation (scalar)
    // d_in[4] = DetectionMap: unused by the reference math (shape only).
    float* out = (float*)d_out;

    precompute_kernel<<<BB * KK, 160>>>(kp, sx, sy, rho);

    dim3 dgrid(HH, BB);
    denom_kernel<<<dgrid, 256>>>();

    dim3 mgrid(BB * KK, 2);
    recon_out_kernel<<<mgrid, 256>>>(out);
}